// round 1
// baseline (speedup 1.0000x reference)
#include <cuda_runtime.h>

#define NB1 296
#define NT1 256
#define NB2 296
#define NT2 256
#define NSTAT 54

// scratch (static device arrays: no allocations)
__device__ float g_partials[NB1 * NSTAT];
__device__ float g_combos[10 * 64];

__device__ __forceinline__ float warp_sum(float v) {
#pragma unroll
    for (int o = 16; o; o >>= 1) v += __shfl_xor_sync(0xffffffffu, v, o);
    return v;
}

#define XOFF ((float)(0.16 / 2.0 + 0.0))
#define YOFF ((float)(0.16 / 2.0 - 39.68))

// Pass 1: accumulate 9 feature sums + 45 upper-triangle second moments of the
// 9-channel augmented features over all valid (pillar, point) pairs.
// One warp per pillar; lane n owns point slot n.
__global__ void __launch_bounds__(NT1) pass1_kernel(
    const float4* __restrict__ in4, const int* __restrict__ npts,
    const int* __restrict__ coords, int P) {
    int lane = threadIdx.x & 31;
    int wid = threadIdx.x >> 5;
    int gw = (blockIdx.x * NT1 + threadIdx.x) >> 5;
    int nw = (gridDim.x * NT1) >> 5;

    float s1[9];
    float s2[45];
#pragma unroll
    for (int i = 0; i < 9; i++) s1[i] = 0.f;
#pragma unroll
    for (int i = 0; i < 45; i++) s2[i] = 0.f;

    for (int p = gw; p < P; p += nw) {
        float4 pt = in4[p * 32 + lane];
        float sx = warp_sum(pt.x);
        float sy = warp_sum(pt.y);
        float sz = warp_sum(pt.z);
        int np = npts[p];
        float rnp = 1.0f / (float)np;
        float mx = sx * rnp, my = sy * rnp, mz = sz * rnp;
        float cx = (float)coords[p * 4 + 3] * 0.16f + XOFF;
        float cy = (float)coords[p * 4 + 2] * 0.16f + YOFF;
        if (lane < np) {
            float f[9];
            f[0] = pt.x; f[1] = pt.y; f[2] = pt.z; f[3] = pt.w;
            f[4] = pt.x - mx; f[5] = pt.y - my; f[6] = pt.z - mz;
            f[7] = pt.x - cx; f[8] = pt.y - cy;
#pragma unroll
            for (int i = 0; i < 9; i++) s1[i] += f[i];
            int k = 0;
#pragma unroll
            for (int i = 0; i < 9; i++)
#pragma unroll
                for (int j = i; j < 9; j++) {
                    s2[k] = fmaf(f[i], f[j], s2[k]);
                    k++;
                }
        }
    }

    // warp reduce all 54 accumulators, then block reduce via shared
    __shared__ float red[NT1 / 32][NSTAT];
#pragma unroll
    for (int i = 0; i < 9; i++) s1[i] = warp_sum(s1[i]);
#pragma unroll
    for (int i = 0; i < 45; i++) s2[i] = warp_sum(s2[i]);
    if (lane == 0) {
#pragma unroll
        for (int i = 0; i < 9; i++) red[wid][i] = s1[i];
#pragma unroll
        for (int i = 0; i < 45; i++) red[wid][9 + i] = s2[i];
    }
    __syncthreads();
    if (threadIdx.x < NSTAT) {
        float v = 0.f;
#pragma unroll
        for (int w = 0; w < NT1 / 32; w++) v += red[w][threadIdx.x];
        g_partials[blockIdx.x * NSTAT + threadIdx.x] = v;
    }
}

// Finalize: reduce per-block partials, derive per-channel mean/var from the
// 9x9 moment matrix (mean = s.W/PN, E[x^2] = W^T S W / PN), fold BN scale
// into the collapsed 4-wide weight combos.
__global__ void finalize_kernel(const float* __restrict__ W,
                                const float* __restrict__ gamma,
                                const float* __restrict__ beta,
                                float invPN) {
    __shared__ float st[NSTAT];
    int t = threadIdx.x;
    if (t < NSTAT) {
        float v = 0.f;
#pragma unroll 8
        for (int b = 0; b < NB1; b++) v += g_partials[b * NSTAT + t];
        st[t] = v;
    }
    __syncthreads();
    if (t < 64) {
        float wc[9];
#pragma unroll
        for (int k = 0; k < 9; k++) wc[k] = W[k * 64 + t];
        float mean = 0.f;
#pragma unroll
        for (int k = 0; k < 9; k++) mean = fmaf(st[k], wc[k], mean);
        mean *= invPN;
        float ex2 = 0.f;
        int idx = 9;
#pragma unroll
        for (int i = 0; i < 9; i++)
#pragma unroll
            for (int j = i; j < 9; j++) {
                float coef = (i == j) ? 1.f : 2.f;
                ex2 = fmaf(st[idx] * coef, wc[i] * wc[j], ex2);
                idx++;
            }
        ex2 *= invPN;
        float var = ex2 - mean * mean;
        float a = gamma[t] / sqrtf(var + 1e-3f);
        float b = beta[t] - mean * a;
        g_combos[0 * 64 + t] = a * (wc[0] + wc[4] + wc[7]);  // coeff of px
        g_combos[1 * 64 + t] = a * (wc[1] + wc[5] + wc[8]);  // coeff of py
        g_combos[2 * 64 + t] = a * (wc[2] + wc[6]);          // coeff of pz
        g_combos[3 * 64 + t] = a * wc[3];                    // coeff of pw
        g_combos[4 * 64 + t] = a * wc[4];                    // mean-x coeff
        g_combos[5 * 64 + t] = a * wc[5];
        g_combos[6 * 64 + t] = a * wc[6];
        g_combos[7 * 64 + t] = a * wc[7];                    // cx coeff
        g_combos[8 * 64 + t] = a * wc[8];                    // cy coeff
        g_combos[9 * 64 + t] = b;                            // BN bias
    }
}

// Pass 2: one warp per pillar; lane owns channels (lane, lane+32).
// Points broadcast via shfl; y = relu(px*awx + py*awy + pz*awz + pw*aww + pc),
// max over valid points; masked slots contribute relu(b).
__global__ void __launch_bounds__(NT2) pass2_kernel(
    const float4* __restrict__ in4, const int* __restrict__ npts,
    const int* __restrict__ coords, float* __restrict__ out, int P) {
    int lane = threadIdx.x & 31;
    int gw = (blockIdx.x * NT2 + threadIdx.x) >> 5;
    int nw = (gridDim.x * NT2) >> 5;
    int c0 = lane, c1 = lane + 32;

    float awx0 = g_combos[c0],        awx1 = g_combos[c1];
    float awy0 = g_combos[64 + c0],   awy1 = g_combos[64 + c1];
    float awz0 = g_combos[128 + c0],  awz1 = g_combos[128 + c1];
    float aww0 = g_combos[192 + c0],  aww1 = g_combos[192 + c1];
    float aw40 = g_combos[256 + c0],  aw41 = g_combos[256 + c1];
    float aw50 = g_combos[320 + c0],  aw51 = g_combos[320 + c1];
    float aw60 = g_combos[384 + c0],  aw61 = g_combos[384 + c1];
    float aw70 = g_combos[448 + c0],  aw71 = g_combos[448 + c1];
    float aw80 = g_combos[512 + c0],  aw81 = g_combos[512 + c1];
    float b0   = g_combos[576 + c0],  b1   = g_combos[576 + c1];
    float rb0 = fmaxf(b0, 0.f), rb1 = fmaxf(b1, 0.f);

    for (int p = gw; p < P; p += nw) {
        float4 pt = in4[p * 32 + lane];
        float sx = warp_sum(pt.x);
        float sy = warp_sum(pt.y);
        float sz = warp_sum(pt.z);
        int np = npts[p];
        float rnp = 1.0f / (float)np;
        float mx = sx * rnp, my = sy * rnp, mz = sz * rnp;
        float cx = (float)coords[p * 4 + 3] * 0.16f + XOFF;
        float cy = (float)coords[p * 4 + 2] * 0.16f + YOFF;
        float pc0 = b0 - fmaf(mx, aw40, fmaf(my, aw50, fmaf(mz, aw60,
                     fmaf(cx, aw70, cy * aw80))));
        float pc1 = b1 - fmaf(mx, aw41, fmaf(my, aw51, fmaf(mz, aw61,
                     fmaf(cx, aw71, cy * aw81))));
        int nv = min(np, 32);
        float m0 = (nv < 32) ? rb0 : 0.f;
        float m1 = (nv < 32) ? rb1 : 0.f;
        for (int n = 0; n < nv; n++) {
            float px = __shfl_sync(0xffffffffu, pt.x, n);
            float py = __shfl_sync(0xffffffffu, pt.y, n);
            float pz = __shfl_sync(0xffffffffu, pt.z, n);
            float pw = __shfl_sync(0xffffffffu, pt.w, n);
            float t0 = fmaf(px, awx0, pc0);
            t0 = fmaf(py, awy0, t0);
            t0 = fmaf(pz, awz0, t0);
            t0 = fmaf(pw, aww0, t0);
            float t1 = fmaf(px, awx1, pc1);
            t1 = fmaf(py, awy1, t1);
            t1 = fmaf(pz, awz1, t1);
            t1 = fmaf(pw, aww1, t1);
            m0 = fmaxf(m0, fmaxf(t0, 0.f));
            m1 = fmaxf(m1, fmaxf(t1, 0.f));
        }
        out[p * 64 + c0] = m0;
        out[p * 64 + c1] = m1;
    }
}

extern "C" void kernel_launch(void* const* d_in, const int* in_sizes, int n_in,
                              void* d_out, int out_size) {
    const float4* in4 = (const float4*)d_in[0];
    const int* npts = (const int*)d_in[1];
    const int* coords = (const int*)d_in[2];
    const float* W = (const float*)d_in[3];
    const float* gamma = (const float*)d_in[4];
    const float* beta = (const float*)d_in[5];
    float* out = (float*)d_out;

    int P = in_sizes[1];                 // 30000
    int N = in_sizes[0] / (P * 4);       // 32
    float invPN = 1.0f / ((float)P * (float)N);

    pass1_kernel<<<NB1, NT1>>>(in4, npts, coords, P);
    finalize_kernel<<<1, 128>>>(W, gamma, beta, invPN);
    pass2_kernel<<<NB2, NT2>>>(in4, npts, coords, out, P);
}

// round 2
// speedup vs baseline: 1.7542x; 1.7542x over previous
#include <cuda_runtime.h>

#define NT1 256
#define NT2 256
#define NB2 592
#define NSTAT 54
#define MAXB 512

// scratch (static device arrays: no allocations)
__device__ float g_partials[MAXB * NSTAT];
__device__ float g_combos[10 * 64];

#define XOFF ((float)(0.16 / 2.0 + 0.0))
#define YOFF ((float)(0.16 / 2.0 - 39.68))

__device__ __forceinline__ float warp_sum(float v) {
#pragma unroll
    for (int o = 16; o; o >>= 1) v += __shfl_xor_sync(0xffffffffu, v, o);
    return v;
}

// ---------------------------------------------------------------------------
// Pass 1: two threads per pillar (even/odd point slots). Each thread
// accumulates per-pillar base moments: A1 = sum over ALL slots of xyz,
// V1[4] = sum over valid slots, V2[10] = upper-tri second moments over valid
// slots. Pair-combine via shfl xor 1, then even lanes expand into the 54
// global stats of the 9-channel augmented features:
//   f = (x,y,z,w, x-mx, y-my, z-mz, x-cx, y-cy)
//   sum f_i f_j = V2_ij - off_i V1_j - off_j V1_i + np off_i off_j
// ---------------------------------------------------------------------------
__global__ void __launch_bounds__(NT1) pass1_kernel(
    const float4* __restrict__ in4, const int* __restrict__ npts,
    const int* __restrict__ coords, int P) {
    int g = blockIdx.x * NT1 + threadIdx.x;
    int p = g >> 1;
    int h = g & 1;
    int lane = threadIdx.x & 31;
    int wid = threadIdx.x >> 5;

    float a1x = 0.f, a1y = 0.f, a1z = 0.f;
    float v1[4] = {0.f, 0.f, 0.f, 0.f};
    float v2[10] = {0.f, 0.f, 0.f, 0.f, 0.f, 0.f, 0.f, 0.f, 0.f, 0.f};
    float acc[NSTAT];
#pragma unroll
    for (int i = 0; i < NSTAT; i++) acc[i] = 0.f;

    bool active = (p < P);
    int np = 1;
    float cx = 0.f, cy = 0.f;
    if (active) {
        np = npts[p];
        cx = (float)coords[p * 4 + 3] * 0.16f + XOFF;
        cy = (float)coords[p * 4 + 2] * 0.16f + YOFF;
        const float4* base = in4 + (size_t)p * 32 + h;
#pragma unroll 8
        for (int n = 0; n < 16; n++) {
            float4 pt = base[2 * n];
            a1x += pt.x; a1y += pt.y; a1z += pt.z;
            if (2 * n + h < np) {
                v1[0] += pt.x; v1[1] += pt.y; v1[2] += pt.z; v1[3] += pt.w;
                v2[0] = fmaf(pt.x, pt.x, v2[0]);
                v2[1] = fmaf(pt.x, pt.y, v2[1]);
                v2[2] = fmaf(pt.x, pt.z, v2[2]);
                v2[3] = fmaf(pt.x, pt.w, v2[3]);
                v2[4] = fmaf(pt.y, pt.y, v2[4]);
                v2[5] = fmaf(pt.y, pt.z, v2[5]);
                v2[6] = fmaf(pt.y, pt.w, v2[6]);
                v2[7] = fmaf(pt.z, pt.z, v2[7]);
                v2[8] = fmaf(pt.z, pt.w, v2[8]);
                v2[9] = fmaf(pt.w, pt.w, v2[9]);
            }
        }
    }
    // pair reduce (even+odd halves of the pillar)
    a1x += __shfl_xor_sync(0xffffffffu, a1x, 1);
    a1y += __shfl_xor_sync(0xffffffffu, a1y, 1);
    a1z += __shfl_xor_sync(0xffffffffu, a1z, 1);
#pragma unroll
    for (int i = 0; i < 4; i++) v1[i] += __shfl_xor_sync(0xffffffffu, v1[i], 1);
#pragma unroll
    for (int i = 0; i < 10; i++) v2[i] += __shfl_xor_sync(0xffffffffu, v2[i], 1);

    if (active && h == 0) {
        float npf = (float)np;
        float rnp = 1.f / npf;
        float mx = a1x * rnp, my = a1y * rnp, mz = a1z * rnp;
        const int bi[9] = {0, 1, 2, 3, 0, 1, 2, 0, 1};
        const int sym[4][4] = {{0, 1, 2, 3}, {1, 4, 5, 6}, {2, 5, 7, 8}, {3, 6, 8, 9}};
        float off[9] = {0.f, 0.f, 0.f, 0.f, mx, my, mz, cx, cy};
        float b1v[9];
#pragma unroll
        for (int i = 0; i < 9; i++) b1v[i] = v1[bi[i]];
#pragma unroll
        for (int i = 0; i < 9; i++) acc[i] = b1v[i] - npf * off[i];
        int k = 9;
#pragma unroll
        for (int i = 0; i < 9; i++)
#pragma unroll
            for (int j = i; j < 9; j++) {
                acc[k] = v2[sym[bi[i]][bi[j]]] - off[i] * b1v[j] - off[j] * b1v[i]
                         + npf * off[i] * off[j];
                k++;
            }
    }

    // reduce over even lanes only (odd lanes hold zeros): 4-level butterfly
    __shared__ float red[NT1 / 32][NSTAT];
#pragma unroll
    for (int i = 0; i < NSTAT; i++) {
#pragma unroll
        for (int o = 16; o >= 2; o >>= 1)
            acc[i] += __shfl_xor_sync(0xffffffffu, acc[i], o);
    }
    if (lane == 0) {
#pragma unroll
        for (int i = 0; i < NSTAT; i++) red[wid][i] = acc[i];
    }
    __syncthreads();
    if (threadIdx.x < NSTAT) {
        float v = 0.f;
#pragma unroll
        for (int w = 0; w < NT1 / 32; w++) v += red[w][threadIdx.x];
        g_partials[blockIdx.x * NSTAT + threadIdx.x] = v;
    }
}

// ---------------------------------------------------------------------------
// Finalize: reduce per-block partials (54 stats x 8 reducer rows), derive
// per-channel BN mean/var from the 9x9 moment matrix, fold into collapsed
// 4-wide weight combos + per-pillar-constant coefficients + bias.
// ---------------------------------------------------------------------------
__global__ void finalize_kernel(const float* __restrict__ W,
                                const float* __restrict__ gamma,
                                const float* __restrict__ beta,
                                float invPN, int nb) {
    __shared__ float red[8][NSTAT];
    __shared__ float st[NSTAT];
    int t = threadIdx.x;  // 0..431
    int s = t % NSTAT;
    int r = t / NSTAT;    // 0..7
    if (t < NSTAT * 8) {
        float v = 0.f;
        for (int b = r; b < nb; b += 8) v += g_partials[b * NSTAT + s];
        red[r][s] = v;
    }
    __syncthreads();
    if (t < NSTAT) {
        float x = 0.f;
#pragma unroll
        for (int r2 = 0; r2 < 8; r2++) x += red[r2][t];
        st[t] = x;
    }
    __syncthreads();
    if (t < 64) {
        float wc[9];
#pragma unroll
        for (int k = 0; k < 9; k++) wc[k] = W[k * 64 + t];
        float mean = 0.f;
#pragma unroll
        for (int k = 0; k < 9; k++) mean = fmaf(st[k], wc[k], mean);
        mean *= invPN;
        float ex2 = 0.f;
        int idx = 9;
#pragma unroll
        for (int i = 0; i < 9; i++)
#pragma unroll
            for (int j = i; j < 9; j++) {
                float coef = (i == j) ? 1.f : 2.f;
                ex2 = fmaf(st[idx] * coef, wc[i] * wc[j], ex2);
                idx++;
            }
        ex2 *= invPN;
        float var = ex2 - mean * mean;
        float a = gamma[t] / sqrtf(var + 1e-3f);
        float b = beta[t] - mean * a;
        g_combos[0 * 64 + t] = a * (wc[0] + wc[4] + wc[7]);  // coeff of px
        g_combos[1 * 64 + t] = a * (wc[1] + wc[5] + wc[8]);  // coeff of py
        g_combos[2 * 64 + t] = a * (wc[2] + wc[6]);          // coeff of pz
        g_combos[3 * 64 + t] = a * wc[3];                    // coeff of pw
        g_combos[4 * 64 + t] = a * wc[4];                    // mean-x coeff
        g_combos[5 * 64 + t] = a * wc[5];
        g_combos[6 * 64 + t] = a * wc[6];
        g_combos[7 * 64 + t] = a * wc[7];                    // cx coeff
        g_combos[8 * 64 + t] = a * wc[8];                    // cy coeff
        g_combos[9 * 64 + t] = b;                            // BN bias
    }
}

// ---------------------------------------------------------------------------
// Pass 2: one warp per pillar; lane owns channels (lane, lane+32).
// Points staged to shared, broadcast-read in the inner loop (no shfls).
// relu/max commute: M = max_n t_n (pc-free), result = relu(M + pc), with
// masked-slot contribution relu(b) when nv < 32.
// ---------------------------------------------------------------------------
__global__ void __launch_bounds__(NT2) pass2_kernel(
    const float4* __restrict__ in4, const int* __restrict__ npts,
    const int* __restrict__ coords, float* __restrict__ out, int P) {
    __shared__ float4 tile[NT2 / 32][32];
    int lane = threadIdx.x & 31;
    int wid = threadIdx.x >> 5;
    int gw = (blockIdx.x * NT2 + threadIdx.x) >> 5;
    int nw = (gridDim.x * NT2) >> 5;
    int c0 = lane, c1 = lane + 32;

    float wx0 = g_combos[c0],       wx1 = g_combos[c1];
    float wy0 = g_combos[64 + c0],  wy1 = g_combos[64 + c1];
    float wz0 = g_combos[128 + c0], wz1 = g_combos[128 + c1];
    float ww0 = g_combos[192 + c0], ww1 = g_combos[192 + c1];
    float a40 = g_combos[256 + c0], a41 = g_combos[256 + c1];
    float a50 = g_combos[320 + c0], a51 = g_combos[320 + c1];
    float a60 = g_combos[384 + c0], a61 = g_combos[384 + c1];
    float a70 = g_combos[448 + c0], a71 = g_combos[448 + c1];
    float a80 = g_combos[512 + c0], a81 = g_combos[512 + c1];
    float b0  = g_combos[576 + c0], b1  = g_combos[576 + c1];
    float rb0 = fmaxf(b0, 0.f), rb1 = fmaxf(b1, 0.f);

    for (int p = gw; p < P; p += nw) {
        float4 pt = in4[(size_t)p * 32 + lane];
        tile[wid][lane] = pt;
        __syncwarp();
        int np = npts[p];
        float sx = warp_sum(pt.x);
        float sy = warp_sum(pt.y);
        float sz = warp_sum(pt.z);
        int nv = min(np, 32);
        float M0 = -3.0e38f, M1 = -3.0e38f;
#pragma unroll 4
        for (int n = 0; n < nv; n++) {
            float4 q = tile[wid][n];
            float t0 = fmaf(q.x, wx0, fmaf(q.y, wy0, fmaf(q.z, wz0, q.w * ww0)));
            float t1 = fmaf(q.x, wx1, fmaf(q.y, wy1, fmaf(q.z, wz1, q.w * ww1)));
            M0 = fmaxf(M0, t0);
            M1 = fmaxf(M1, t1);
        }
        float rnp = 1.0f / (float)np;
        float mx = sx * rnp, my = sy * rnp, mz = sz * rnp;
        float cx = (float)coords[p * 4 + 3] * 0.16f + XOFF;
        float cy = (float)coords[p * 4 + 2] * 0.16f + YOFF;
        float pc0 = b0 - fmaf(mx, a40, fmaf(my, a50, fmaf(mz, a60,
                     fmaf(cx, a70, cy * a80))));
        float pc1 = b1 - fmaf(mx, a41, fmaf(my, a51, fmaf(mz, a61,
                     fmaf(cx, a71, cy * a81))));
        float r0 = fmaxf(M0 + pc0, 0.f);
        float r1 = fmaxf(M1 + pc1, 0.f);
        if (nv < 32) { r0 = fmaxf(r0, rb0); r1 = fmaxf(r1, rb1); }
        out[(size_t)p * 64 + c0] = r0;
        out[(size_t)p * 64 + c1] = r1;
        __syncwarp();  // protect tile before next iteration's overwrite
    }
}

extern "C" void kernel_launch(void* const* d_in, const int* in_sizes, int n_in,
                              void* d_out, int out_size) {
    const float4* in4 = (const float4*)d_in[0];
    const int* npts = (const int*)d_in[1];
    const int* coords = (const int*)d_in[2];
    const float* W = (const float*)d_in[3];
    const float* gamma = (const float*)d_in[4];
    const float* beta = (const float*)d_in[5];
    float* out = (float*)d_out;

    int P = in_sizes[1];                 // 30000
    int N = in_sizes[0] / (P * 4);       // 32
    float invPN = 1.0f / ((float)P * (float)N);

    int nb1 = (2 * P + NT1 - 1) / NT1;   // 235 for P=30000
    if (nb1 > MAXB) nb1 = MAXB;          // (problem sizes fixed; safety clamp)

    pass1_kernel<<<nb1, NT1>>>(in4, npts, coords, P);
    finalize_kernel<<<1, NSTAT * 8>>>(W, gamma, beta, invPN, nb1);
    pass2_kernel<<<NB2, NT2>>>(in4, npts, coords, out, P);
}